// round 15
// baseline (speedup 1.0000x reference)
#include <cuda_runtime.h>
#include <cuda_fp16.h>
#include <cstdint>

// Convolution_22600117912286: continuous convolution with Gaussian radial basis.
// out[z,a,i] = (1/sqrt(n_norm)) * sum_b sum_c exp(-((d_ab - c*w)/w)^2) * G[z,b,c,i]
//   where G[z,b,c,i] = sum_j W[c,i,j] * features[z,b,j]
// Shapes: B=2, N=1024, D_IN=8, D_OUT=8, C=32, R_MAX=3.5, w=3.5/31.
//
// R14 = R13 with the build break fixed (<cstdint>; prefetch lambda -> helper).
//  - cp.async double-buffered G staging (prefetch t+2 during compute of t).
//  - Pad rows eliminated: w0 = clamp(floor(u0-3), 0, 24) keeps the 8-tap
//    window exact for all in-range centers; two 24KB buffers = 48KB smem.
//  - SPLIT 4; geometry read directly from L1 (sgeo removed).
//  - Final SPLIT-reduction fused into conv via arrival counter (fixed sp
//    order -> deterministic; counter self-resets for graph replay).
//  - prep: W staged in conflict-free padded smem, 512 blocks.

#define BATCH   2
#define NPTS    1024
#define NC      32
#define RMAXF   3.5f
#define TILE_A  32
#define SPLIT   4
#define B_TILE  16
#define RSTRIDE 24                 // halves per (b,k) row: 8 data + 16 pad = 48B
#define BUFH    (B_TILE * NC * RSTRIDE)        // 12288 halves = 24576 B per buffer
#define NT      ((NPTS / SPLIT) / B_TILE)      // 16 tiles

// scratch (no allocations allowed -> __device__ globals)
__device__ __align__(16) __half2 g_Gh[BATCH * NPTS * NC * 4];   // 1 MB (half2 units)
__device__ float g_partial[SPLIT * BATCH * NPTS * 8];           // 256 KB
__device__ int   g_cnt[BATCH * (NPTS / TILE_A)];                // 64 counters, 0-init

// ---------------------------------------------------------------------------
// Kernel 1: G[z,b,c,i] = scale * sum_j W[c,i,j] * f[z,b,j], stored fp16.
// 512 blocks; block covers 4 zb rows x 128 column-pairs. W staged in smem with
// 80B row stride (20 floats: 16 data + 4 pad -> conflict-free LDS.128).
// ---------------------------------------------------------------------------
__global__ __launch_bounds__(256)
void prep_G_kernel(const float* __restrict__ feat,
                   const float* __restrict__ W,
                   const int* __restrict__ n_norm)
{
    __shared__ __align__(16) float sW[128 * 20];    // 10 KB, padded rows
    __shared__ __align__(16) float sf[32];          // 4 zb x 8 feats

    const int tid = threadIdx.x;
    const int zb0 = blockIdx.x * 4;

    // stage W: 512 float4 -> padded rows (cp = q>>2, part = q&3)
#pragma unroll
    for (int it = 0; it < 2; ++it) {
        int q  = tid + it * 256;
        float4 v = __ldg(reinterpret_cast<const float4*>(W) + q);
        int cp = q >> 2, part = q & 3;
        *reinterpret_cast<float4*>(&sW[cp * 20 + part * 4]) = v;
    }
    if (tid < 32) sf[tid] = __ldg(feat + zb0 * 8 + tid);
    __syncthreads();

    const float scale = rsqrtf((float)(*n_norm));
    const int cp  = tid & 127;
    const int zh  = (tid >> 7) * 2;                 // handles zb_l = zh, zh+1

    float4 wa0 = *reinterpret_cast<const float4*>(&sW[cp * 20 + 0]);
    float4 wb0 = *reinterpret_cast<const float4*>(&sW[cp * 20 + 4]);
    float4 wa1 = *reinterpret_cast<const float4*>(&sW[cp * 20 + 8]);
    float4 wb1 = *reinterpret_cast<const float4*>(&sW[cp * 20 + 12]);

#pragma unroll
    for (int zz = 0; zz < 2; ++zz) {
        const int zb_l = zh + zz;
        float4 fa = *reinterpret_cast<const float4*>(&sf[zb_l * 8]);
        float4 fb = *reinterpret_cast<const float4*>(&sf[zb_l * 8 + 4]);
        float s0 = wa0.x * fa.x;
        s0 = fmaf(wa0.y, fa.y, s0); s0 = fmaf(wa0.z, fa.z, s0); s0 = fmaf(wa0.w, fa.w, s0);
        s0 = fmaf(wb0.x, fb.x, s0); s0 = fmaf(wb0.y, fb.y, s0);
        s0 = fmaf(wb0.z, fb.z, s0); s0 = fmaf(wb0.w, fb.w, s0);
        float s1 = wa1.x * fa.x;
        s1 = fmaf(wa1.y, fa.y, s1); s1 = fmaf(wa1.z, fa.z, s1); s1 = fmaf(wa1.w, fa.w, s1);
        s1 = fmaf(wb1.x, fb.x, s1); s1 = fmaf(wb1.y, fb.y, s1);
        s1 = fmaf(wb1.z, fb.z, s1); s1 = fmaf(wb1.w, fb.w, s1);
        g_Gh[(size_t)(zb0 + zb_l) * 128 + cp] = __floats2half2_rn(s0 * scale, s1 * scale);
    }
}

// ---------------------------------------------------------------------------
// cp.async helpers
// ---------------------------------------------------------------------------
__device__ __forceinline__ void cp_async16(uint32_t dst_smem, const void* src)
{
    asm volatile("cp.async.cg.shared.global [%0], [%1], 16;"
                 :: "r"(dst_smem), "l"(src) : "memory");
}
__device__ __forceinline__ void cp_commit()
{
    asm volatile("cp.async.commit_group;" ::: "memory");
}
template <int N>
__device__ __forceinline__ void cp_wait()
{
    asm volatile("cp.async.wait_group %0;" :: "n"(N) : "memory");
}

// prefetch tile tt of this block's b-range into buffer (tt & 1)
__device__ __forceinline__ void prefetch_tile(const uint4* gsrc, uint32_t smem_base,
                                              int tid, int tt)
{
    const uint4* src = gsrc + tt * (B_TILE * NC);
    uint32_t bufb = smem_base + (uint32_t)(tt & 1) * (uint32_t)(BUFH * 2);
#pragma unroll
    for (int it = 0; it < 2; ++it) {
        int q  = tid + it * 256;           // 0..511
        int k  = q & (NC - 1);
        int bl = q >> 5;
        cp_async16(bufb + (uint32_t)(bl * NC + k) * 48u, src + q);
    }
    cp_commit();
}

// ---------------------------------------------------------------------------
// Kernel 2: pairwise contraction + fused SPLIT reduction.
// Block = (z, a-tile of 32, b-split of 256). Warp owns 4 a's; lanes = (p, j).
// Tap window k = w0..w0+7 with w0 = clamp(floor(u0-3), 0, 24): exact for all
// centers within 4 widths; m capped at 14 (far pairs -> weights underflow).
// ---------------------------------------------------------------------------
__global__ __launch_bounds__(256)
void conv_kernel(const float* __restrict__ geom, float* __restrict__ out)
{
    __shared__ __align__(16) __half sGh[2 * BUFH];  // 49152 B exactly

    const int tid     = threadIdx.x;
    const int z       = blockIdx.z;
    const int a0      = blockIdx.x * TILE_A;
    const int bsplit0 = blockIdx.y * (NPTS / SPLIT);
    const int wid     = tid >> 5;              // 0..7
    const int lane    = tid & 31;
    const int p       = lane >> 3;             // a-subgroup 0..3
    const int j       = lane & 7;              // tap index 0..7
    const float jf    = (float)j;
    const int   joff  = j * (RSTRIDE * 2);     // tap byte offset (48B rows)

    const uint32_t smem_base = (uint32_t)__cvta_generic_to_shared(sGh);
    const uint4* gsrc = reinterpret_cast<const uint4*>(g_Gh)
                      + (size_t)(z * NPTS + bsplit0) * NC;

    prefetch_tile(gsrc, smem_base, tid, 0);
    prefetch_tile(gsrc, smem_base, tid, 1);

    const int   a  = a0 + wid * 4 + p;         // this lane's output point
    const float ax = __ldg(geom + (z * NPTS + a) * 3 + 0);
    const float ay = __ldg(geom + (z * NPTS + a) * 3 + 1);
    const float az = __ldg(geom + (z * NPTS + a) * 3 + 2);

    const float INV_W  = (float)(NC - 1) / RMAXF;      // 31/3.5
    const float NLOG2E = -1.4426950408889634f;         // -log2(e)

    float acc0 = 0.f, acc1 = 0.f, acc2 = 0.f, acc3 = 0.f;
    float acc4 = 0.f, acc5 = 0.f, acc6 = 0.f, acc7 = 0.f;

    for (int t = 0; t < NT; ++t) {
        if (t + 1 < NT) cp_wait<1>(); else cp_wait<0>();
        __syncthreads();                       // tile t visible; prev compute done

        const int bt = bsplit0 + t * B_TILE;
        const int bufoff = (t & 1) * (BUFH * 2);   // byte offset of active buffer

#pragma unroll
        for (int r = 0; r < 2; ++r) {          // two groups of 8 b's
            // lane (p, q=j) computes window params for (a_p, b_{r*8+q})
            const int bl = r * 8 + j;
            const float* gb = geom + (size_t)(z * NPTS + bt + bl) * 3;
            float dx = ax - __ldg(gb + 0);
            float dy = ay - __ldg(gb + 1);
            float dz = az - __ldg(gb + 2);
            float d2 = fmaf(dx, dx, fmaf(dy, dy, fmaf(dz, dz, 1e-12f)));
            float u0 = sqrtf(d2) * INV_W;
            float w0f = fminf(fmaxf(floorf(u0 - 3.0f), 0.0f), 24.0f);
            float m   = u0 - w0f;
            int   A   = bufoff + (bl * NC + (int)w0f) * 48;   // byte offset

            __half2 h2z = __float2half2_rn(0.0f);
            __half2 hc0 = h2z, hc1 = h2z, hc2 = h2z, hc3 = h2z;

#pragma unroll
            for (int bsub = 0; bsub < 8; ++bsub) {
                int   srcl = (lane & 24) + bsub;
                float mb = __shfl_sync(0xffffffffu, m, srcl);
                int   Ab = __shfl_sync(0xffffffffu, A, srcl);
                float dj = fminf(mb, 14.0f) - jf;
                float w  = exp2f(dj * dj * NLOG2E);        // exp(-(m-j)^2)
                __half2 wh = __float2half2_rn(w);
                uint4 raw = *reinterpret_cast<const uint4*>(
                    reinterpret_cast<const char*>(sGh) + (Ab + joff));
                hc0 = __hfma2(*reinterpret_cast<__half2*>(&raw.x), wh, hc0);
                hc1 = __hfma2(*reinterpret_cast<__half2*>(&raw.y), wh, hc1);
                hc2 = __hfma2(*reinterpret_cast<__half2*>(&raw.z), wh, hc2);
                hc3 = __hfma2(*reinterpret_cast<__half2*>(&raw.w), wh, hc3);
            }
            float2 f0 = __half22float2(hc0);
            float2 f1 = __half22float2(hc1);
            float2 f2 = __half22float2(hc2);
            float2 f3 = __half22float2(hc3);
            acc0 += f0.x; acc1 += f0.y; acc2 += f1.x; acc3 += f1.y;
            acc4 += f2.x; acc5 += f2.y; acc6 += f3.x; acc7 += f3.y;
        }

        __syncthreads();                       // all warps done reading buffer
        if (t + 2 < NT) prefetch_tile(gsrc, smem_base, tid, t + 2);
    }

    // reduce over the 8 tap-lanes of each a-subgroup
#pragma unroll
    for (int st = 1; st < 8; st <<= 1) {
        acc0 += __shfl_xor_sync(0xffffffffu, acc0, st);
        acc1 += __shfl_xor_sync(0xffffffffu, acc1, st);
        acc2 += __shfl_xor_sync(0xffffffffu, acc2, st);
        acc3 += __shfl_xor_sync(0xffffffffu, acc3, st);
        acc4 += __shfl_xor_sync(0xffffffffu, acc4, st);
        acc5 += __shfl_xor_sync(0xffffffffu, acc5, st);
        acc6 += __shfl_xor_sync(0xffffffffu, acc6, st);
        acc7 += __shfl_xor_sync(0xffffffffu, acc7, st);
    }
    if (j == 0) {
        float* dst = g_partial
                   + ((size_t)(blockIdx.y * BATCH + z) * NPTS + a) * 8;
        *reinterpret_cast<float4*>(dst)     = make_float4(acc0, acc1, acc2, acc3);
        *reinterpret_cast<float4*>(dst + 4) = make_float4(acc4, acc5, acc6, acc7);
    }

    // ---- fused SPLIT reduction: last block of the 4 for this (z, a-tile) ----
    __syncthreads();                           // all partial stores issued
    int* sflag = reinterpret_cast<int*>(sGh);
    if (tid == 0) {
        __threadfence();                       // release partials
        int old = atomicAdd(&g_cnt[z * (NPTS / TILE_A) + blockIdx.x], 1);
        sflag[0] = (old == SPLIT - 1);
        if (old == SPLIT - 1) __threadfence(); // acquire other blocks' partials
    }
    __syncthreads();
    if (sflag[0]) {
        int al = tid >> 3;                     // 0..31
        int i  = tid & 7;                      // 0..7
        int aa = a0 + al;
        float s = 0.0f;
#pragma unroll
        for (int sp = 0; sp < SPLIT; ++sp)
            s += __ldcg(g_partial + ((size_t)(sp * BATCH + z) * NPTS + aa) * 8 + i);
        out[((size_t)z * NPTS + aa) * 8 + i] = s;
        if (tid == 0) g_cnt[z * (NPTS / TILE_A) + blockIdx.x] = 0;  // reset for replay
    }
}

extern "C" void kernel_launch(void* const* d_in, const int* in_sizes, int n_in,
                              void* d_out, int out_size)
{
    const float* features = (const float*)d_in[0];   // [2,1024,8]
    const float* geometry = (const float*)d_in[1];   // [2,1024,3]
    const float* W        = (const float*)d_in[2];   // [32,8,8]
    const int*   n_norm   = (const int*)d_in[3];     // scalar
    float*       out      = (float*)d_out;           // [2,1024,8]

    prep_G_kernel<<<(BATCH * NPTS) / 4, 256>>>(features, W, n_norm);
    conv_kernel<<<dim3(NPTS / TILE_A, SPLIT, BATCH), 256>>>(geometry, out);
}

// round 16
// speedup vs baseline: 1.0846x; 1.0846x over previous
#include <cuda_runtime.h>
#include <cuda_fp16.h>
#include <cstdint>

// Convolution_22600117912286: continuous convolution with Gaussian radial basis.
// out[z,a,i] = (1/sqrt(n_norm)) * sum_b sum_c exp(-((d_ab - c*w)/w)^2) * G[z,b,c,i]
//   where G[z,b,c,i] = sum_j W[c,i,j] * features[z,b,j]
// Shapes: B=2, N=1024, D_IN=8, D_OUT=8, C=32, R_MAX=3.5, w=3.5/31.
//
// R15 changes vs R14 (conv was occupancy-bound: 1.73 blocks/SM, issue 44%):
//  - SPLIT 4 -> 8: 512 blocks, 3.46 blocks/SM, ~28 warps/SM. cp.async
//    double-buffering now has warps to overlap with.
//  - m-clamp removed (EX2 underflows to 0 for far pairs anyway).
//  - srcl base hoisted out of the inner loop.

#define BATCH   2
#define NPTS    1024
#define NC      32
#define RMAXF   3.5f
#define TILE_A  32
#define SPLIT   8
#define B_TILE  16
#define RSTRIDE 24                 // halves per (b,k) row: 8 data + 16 pad = 48B
#define BUFH    (B_TILE * NC * RSTRIDE)        // 12288 halves = 24576 B per buffer
#define NT      ((NPTS / SPLIT) / B_TILE)      // 8 tiles

// scratch (no allocations allowed -> __device__ globals)
__device__ __align__(16) __half2 g_Gh[BATCH * NPTS * NC * 4];   // 1 MB (half2 units)
__device__ float g_partial[SPLIT * BATCH * NPTS * 8];           // 512 KB
__device__ int   g_cnt[BATCH * (NPTS / TILE_A)];                // 64 counters, 0-init

// ---------------------------------------------------------------------------
// Kernel 1: G[z,b,c,i] = scale * sum_j W[c,i,j] * f[z,b,j], stored fp16.
// 512 blocks; block covers 4 zb rows x 128 column-pairs. W staged in smem with
// 80B row stride (20 floats: 16 data + 4 pad -> conflict-free LDS.128).
// ---------------------------------------------------------------------------
__global__ __launch_bounds__(256)
void prep_G_kernel(const float* __restrict__ feat,
                   const float* __restrict__ W,
                   const int* __restrict__ n_norm)
{
    __shared__ __align__(16) float sW[128 * 20];    // 10 KB, padded rows
    __shared__ __align__(16) float sf[32];          // 4 zb x 8 feats

    const int tid = threadIdx.x;
    const int zb0 = blockIdx.x * 4;

    // stage W: 512 float4 -> padded rows (cp = q>>2, part = q&3)
#pragma unroll
    for (int it = 0; it < 2; ++it) {
        int q  = tid + it * 256;
        float4 v = __ldg(reinterpret_cast<const float4*>(W) + q);
        int cp = q >> 2, part = q & 3;
        *reinterpret_cast<float4*>(&sW[cp * 20 + part * 4]) = v;
    }
    if (tid < 32) sf[tid] = __ldg(feat + zb0 * 8 + tid);
    __syncthreads();

    const float scale = rsqrtf((float)(*n_norm));
    const int cp  = tid & 127;
    const int zh  = (tid >> 7) * 2;                 // handles zb_l = zh, zh+1

    float4 wa0 = *reinterpret_cast<const float4*>(&sW[cp * 20 + 0]);
    float4 wb0 = *reinterpret_cast<const float4*>(&sW[cp * 20 + 4]);
    float4 wa1 = *reinterpret_cast<const float4*>(&sW[cp * 20 + 8]);
    float4 wb1 = *reinterpret_cast<const float4*>(&sW[cp * 20 + 12]);

#pragma unroll
    for (int zz = 0; zz < 2; ++zz) {
        const int zb_l = zh + zz;
        float4 fa = *reinterpret_cast<const float4*>(&sf[zb_l * 8]);
        float4 fb = *reinterpret_cast<const float4*>(&sf[zb_l * 8 + 4]);
        float s0 = wa0.x * fa.x;
        s0 = fmaf(wa0.y, fa.y, s0); s0 = fmaf(wa0.z, fa.z, s0); s0 = fmaf(wa0.w, fa.w, s0);
        s0 = fmaf(wb0.x, fb.x, s0); s0 = fmaf(wb0.y, fb.y, s0);
        s0 = fmaf(wb0.z, fb.z, s0); s0 = fmaf(wb0.w, fb.w, s0);
        float s1 = wa1.x * fa.x;
        s1 = fmaf(wa1.y, fa.y, s1); s1 = fmaf(wa1.z, fa.z, s1); s1 = fmaf(wa1.w, fa.w, s1);
        s1 = fmaf(wb1.x, fb.x, s1); s1 = fmaf(wb1.y, fb.y, s1);
        s1 = fmaf(wb1.z, fb.z, s1); s1 = fmaf(wb1.w, fb.w, s1);
        g_Gh[(size_t)(zb0 + zb_l) * 128 + cp] = __floats2half2_rn(s0 * scale, s1 * scale);
    }
}

// ---------------------------------------------------------------------------
// cp.async helpers
// ---------------------------------------------------------------------------
__device__ __forceinline__ void cp_async16(uint32_t dst_smem, const void* src)
{
    asm volatile("cp.async.cg.shared.global [%0], [%1], 16;"
                 :: "r"(dst_smem), "l"(src) : "memory");
}
__device__ __forceinline__ void cp_commit()
{
    asm volatile("cp.async.commit_group;" ::: "memory");
}
template <int N>
__device__ __forceinline__ void cp_wait()
{
    asm volatile("cp.async.wait_group %0;" :: "n"(N) : "memory");
}

// prefetch tile tt of this block's b-range into buffer (tt & 1)
__device__ __forceinline__ void prefetch_tile(const uint4* gsrc, uint32_t smem_base,
                                              int tid, int tt)
{
    const uint4* src = gsrc + tt * (B_TILE * NC);
    uint32_t bufb = smem_base + (uint32_t)(tt & 1) * (uint32_t)(BUFH * 2);
#pragma unroll
    for (int it = 0; it < 2; ++it) {
        int q  = tid + it * 256;           // 0..511
        int k  = q & (NC - 1);
        int bl = q >> 5;
        cp_async16(bufb + (uint32_t)(bl * NC + k) * 48u, src + q);
    }
    cp_commit();
}

// ---------------------------------------------------------------------------
// Kernel 2: pairwise contraction + fused SPLIT reduction.
// Block = (z, a-tile of 32, b-split of 128). Warp owns 4 a's; lanes = (p, j).
// Tap window k = w0..w0+7 with w0 = clamp(floor(u0-3), 0, 24): exact for all
// centers within 4 widths; far pairs' weights underflow to 0 in EX2.
// ---------------------------------------------------------------------------
__global__ __launch_bounds__(256)
void conv_kernel(const float* __restrict__ geom, float* __restrict__ out)
{
    __shared__ __align__(16) __half sGh[2 * BUFH];  // 49152 B exactly

    const int tid     = threadIdx.x;
    const int z       = blockIdx.z;
    const int a0      = blockIdx.x * TILE_A;
    const int bsplit0 = blockIdx.y * (NPTS / SPLIT);
    const int wid     = tid >> 5;              // 0..7
    const int lane    = tid & 31;
    const int p       = lane >> 3;             // a-subgroup 0..3
    const int j       = lane & 7;              // tap index 0..7
    const int srclb   = lane & 24;             // shfl source base (p*8)
    const float jf    = (float)j;
    const int   joff  = j * (RSTRIDE * 2);     // tap byte offset (48B rows)

    const uint32_t smem_base = (uint32_t)__cvta_generic_to_shared(sGh);
    const uint4* gsrc = reinterpret_cast<const uint4*>(g_Gh)
                      + (size_t)(z * NPTS + bsplit0) * NC;

    prefetch_tile(gsrc, smem_base, tid, 0);
    prefetch_tile(gsrc, smem_base, tid, 1);

    const int   a  = a0 + wid * 4 + p;         // this lane's output point
    const float ax = __ldg(geom + (z * NPTS + a) * 3 + 0);
    const float ay = __ldg(geom + (z * NPTS + a) * 3 + 1);
    const float az = __ldg(geom + (z * NPTS + a) * 3 + 2);

    const float INV_W  = (float)(NC - 1) / RMAXF;      // 31/3.5
    const float NLOG2E = -1.4426950408889634f;         // -log2(e)

    float acc0 = 0.f, acc1 = 0.f, acc2 = 0.f, acc3 = 0.f;
    float acc4 = 0.f, acc5 = 0.f, acc6 = 0.f, acc7 = 0.f;

    for (int t = 0; t < NT; ++t) {
        if (t + 1 < NT) cp_wait<1>(); else cp_wait<0>();
        __syncthreads();                       // tile t visible; prev compute done

        const int bt = bsplit0 + t * B_TILE;
        const int bufoff = (t & 1) * (BUFH * 2);   // byte offset of active buffer

#pragma unroll
        for (int r = 0; r < 2; ++r) {          // two groups of 8 b's
            // lane (p, q=j) computes window params for (a_p, b_{r*8+q})
            const int bl = r * 8 + j;
            const float* gb = geom + (size_t)(z * NPTS + bt + bl) * 3;
            float dx = ax - __ldg(gb + 0);
            float dy = ay - __ldg(gb + 1);
            float dz = az - __ldg(gb + 2);
            float d2 = fmaf(dx, dx, fmaf(dy, dy, fmaf(dz, dz, 1e-12f)));
            float u0 = sqrtf(d2) * INV_W;
            float w0f = fminf(fmaxf(floorf(u0 - 3.0f), 0.0f), 24.0f);
            float m   = u0 - w0f;
            int   A   = bufoff + (bl * NC + (int)w0f) * 48;   // byte offset

            __half2 h2z = __float2half2_rn(0.0f);
            __half2 hc0 = h2z, hc1 = h2z, hc2 = h2z, hc3 = h2z;

#pragma unroll
            for (int bsub = 0; bsub < 8; ++bsub) {
                float mb = __shfl_sync(0xffffffffu, m, srclb + bsub);
                int   Ab = __shfl_sync(0xffffffffu, A, srclb + bsub);
                float dj = mb - jf;
                float w  = exp2f(dj * dj * NLOG2E);        // exp(-(m-j)^2)
                __half2 wh = __float2half2_rn(w);
                uint4 raw = *reinterpret_cast<const uint4*>(
                    reinterpret_cast<const char*>(sGh) + (Ab + joff));
                hc0 = __hfma2(*reinterpret_cast<__half2*>(&raw.x), wh, hc0);
                hc1 = __hfma2(*reinterpret_cast<__half2*>(&raw.y), wh, hc1);
                hc2 = __hfma2(*reinterpret_cast<__half2*>(&raw.z), wh, hc2);
                hc3 = __hfma2(*reinterpret_cast<__half2*>(&raw.w), wh, hc3);
            }
            float2 f0 = __half22float2(hc0);
            float2 f1 = __half22float2(hc1);
            float2 f2 = __half22float2(hc2);
            float2 f3 = __half22float2(hc3);
            acc0 += f0.x; acc1 += f0.y; acc2 += f1.x; acc3 += f1.y;
            acc4 += f2.x; acc5 += f2.y; acc6 += f3.x; acc7 += f3.y;
        }

        __syncthreads();                       // all warps done reading buffer
        if (t + 2 < NT) prefetch_tile(gsrc, smem_base, tid, t + 2);
    }

    // reduce over the 8 tap-lanes of each a-subgroup
#pragma unroll
    for (int st = 1; st < 8; st <<= 1) {
        acc0 += __shfl_xor_sync(0xffffffffu, acc0, st);
        acc1 += __shfl_xor_sync(0xffffffffu, acc1, st);
        acc2 += __shfl_xor_sync(0xffffffffu, acc2, st);
        acc3 += __shfl_xor_sync(0xffffffffu, acc3, st);
        acc4 += __shfl_xor_sync(0xffffffffu, acc4, st);
        acc5 += __shfl_xor_sync(0xffffffffu, acc5, st);
        acc6 += __shfl_xor_sync(0xffffffffu, acc6, st);
        acc7 += __shfl_xor_sync(0xffffffffu, acc7, st);
    }
    if (j == 0) {
        float* dst = g_partial
                   + ((size_t)(blockIdx.y * BATCH + z) * NPTS + a) * 8;
        *reinterpret_cast<float4*>(dst)     = make_float4(acc0, acc1, acc2, acc3);
        *reinterpret_cast<float4*>(dst + 4) = make_float4(acc4, acc5, acc6, acc7);
    }

    // ---- fused SPLIT reduction: last block of the 8 for this (z, a-tile) ----
    __syncthreads();                           // all partial stores issued
    int* sflag = reinterpret_cast<int*>(sGh);
    if (tid == 0) {
        __threadfence();                       // release partials
        int old = atomicAdd(&g_cnt[z * (NPTS / TILE_A) + blockIdx.x], 1);
        sflag[0] = (old == SPLIT - 1);
        if (old == SPLIT - 1) __threadfence(); // acquire other blocks' partials
    }
    __syncthreads();
    if (sflag[0]) {
        int al = tid >> 3;                     // 0..31
        int i  = tid & 7;                      // 0..7
        int aa = a0 + al;
        float s = 0.0f;
#pragma unroll
        for (int sp = 0; sp < SPLIT; ++sp)
            s += __ldcg(g_partial + ((size_t)(sp * BATCH + z) * NPTS + aa) * 8 + i);
        out[((size_t)z * NPTS + aa) * 8 + i] = s;
        if (tid == 0) g_cnt[z * (NPTS / TILE_A) + blockIdx.x] = 0;  // reset for replay
    }
}

extern "C" void kernel_launch(void* const* d_in, const int* in_sizes, int n_in,
                              void* d_out, int out_size)
{
    const float* features = (const float*)d_in[0];   // [2,1024,8]
    const float* geometry = (const float*)d_in[1];   // [2,1024,3]
    const float* W        = (const float*)d_in[2];   // [32,8,8]
    const int*   n_norm   = (const int*)d_in[3];     // scalar
    float*       out      = (float*)d_out;           // [2,1024,8]

    prep_G_kernel<<<(BATCH * NPTS) / 4, 256>>>(features, W, n_norm);
    conv_kernel<<<dim3(NPTS / TILE_A, SPLIT, BATCH), 256>>>(geometry, out);
}